// round 1
// baseline (speedup 1.0000x reference)
#include <cuda_runtime.h>

#define NDIM 65
#define ND2  (NDIM*NDIM)
#define NV   (NDIM*NDIM*NDIM)          /* 274625 */
#define NVB  ((NV + 255) / 256)        /* 1073   */
#define NT   (64*64*64*6)              /* 1572864 */
#define NTB  ((NT + 255) / 256)        /* 6144   */

// -------- scratch (device globals; no allocations allowed) --------
__device__ unsigned char      g_mask[NV];   // 7-bit crossing mask per vertex
__device__ int                g_vloc[NV];   // exclusive-in-block edge count prefix
__device__ int                g_vblk[NVB];  // block sums -> scanned in place
__device__ unsigned int       g_tloc[NT];   // packed lo16=c1, hi16=c2 exclusive-in-block
__device__ unsigned long long g_tblk[NTB];  // packed lo32=c1, hi32=c2 block sums -> scanned
__device__ int                g_M;          // total crossing edges (verts)
__device__ int                g_F1;         // total 1-tri tets (== f1 face count)

__constant__ signed char c_tri[16][6] = {
  {-1,-1,-1,-1,-1,-1},{1,0,2,-1,-1,-1},{4,0,3,-1,-1,-1},{1,4,2,1,3,4},
  {3,1,5,-1,-1,-1},{2,3,0,2,5,3},{1,4,0,1,5,4},{4,2,5,-1,-1,-1},
  {4,5,2,-1,-1,-1},{4,1,0,4,5,1},{3,2,0,3,5,2},{1,3,5,-1,-1,-1},
  {4,1,2,4,3,1},{3,0,4,-1,-1,-1},{2,0,1,-1,-1,-1},{-1,-1,-1,-1,-1,-1}};
__constant__ signed char c_ntri[16] = {0,1,1,2,1,2,2,1,1,2,2,1,2,1,1,0};
__constant__ signed char c_ea[6] = {0,0,0,1,1,2};
__constant__ signed char c_eb[6] = {1,2,3,2,3,3};

// ---------------- kernel A: vertex crossing masks + block scan ----------------
__global__ void kA(const float* __restrict__ level, const int* __restrict__ thrp) {
    int v = blockIdx.x * 256 + threadIdx.x;
    int cnt = 0;
    unsigned int mask = 0;
    if (v < NV) {
        float thr = (float)thrp[0];
        int i = v / ND2;
        int r = v - i * ND2;
        int j = r / NDIM;
        int k = r - j * NDIM;
        bool o0 = (level[v] - thr) > 0.0f;
        #pragma unroll
        for (int d = 1; d < 8; ++d) {
            int di = d >> 2, dj = (d >> 1) & 1, dk = d & 1;
            if (i + di < NDIM && j + dj < NDIM && k + dk < NDIM) {
                int w = v + di * ND2 + dj * NDIM + dk;
                bool o1 = (level[w] - thr) > 0.0f;
                if (o0 != o1) { mask |= 1u << (d - 1); cnt++; }
            }
        }
    }
    __shared__ int sh[256];
    sh[threadIdx.x] = cnt; __syncthreads();
    #pragma unroll
    for (int o = 1; o < 256; o <<= 1) {
        int x = (threadIdx.x >= o) ? sh[threadIdx.x - o] : 0;
        __syncthreads();
        sh[threadIdx.x] += x;
        __syncthreads();
    }
    if (v < NV) {
        g_mask[v] = (unsigned char)mask;
        g_vloc[v] = sh[threadIdx.x] - cnt;   // exclusive within block
    }
    if (threadIdx.x == 255) g_vblk[blockIdx.x] = sh[255];
}

// ---------------- scan of vertex block sums (single block) ----------------
__global__ void kScanV() {
    __shared__ int sh[1024];
    int carry = 0;
    for (int base = 0; base < NVB; base += 1024) {
        int idx = base + threadIdx.x;
        int val = (idx < NVB) ? g_vblk[idx] : 0;
        sh[threadIdx.x] = val; __syncthreads();
        for (int o = 1; o < 1024; o <<= 1) {
            int x = (threadIdx.x >= o) ? sh[threadIdx.x - o] : 0;
            __syncthreads();
            sh[threadIdx.x] += x;
            __syncthreads();
        }
        if (idx < NVB) g_vblk[idx] = sh[threadIdx.x] - val + carry;
        int tot = sh[1023];
        __syncthreads();
        carry += tot;
    }
    if (threadIdx.x == 0) g_M = carry;
}

// ---------------- kernel tA: tet classification + block scan ----------------
__global__ void ktA(const float* __restrict__ level, const int* __restrict__ tet,
                    const int* __restrict__ thrp) {
    int t = blockIdx.x * 256 + threadIdx.x;
    unsigned int c = 0;
    if (t < NT) {
        float thr = (float)thrp[0];
        int4 q = ((const int4*)tet)[t];
        int ti = (int)((level[q.x] - thr) > 0.0f)
               | ((int)((level[q.y] - thr) > 0.0f) << 1)
               | ((int)((level[q.z] - thr) > 0.0f) << 2)
               | ((int)((level[q.w] - thr) > 0.0f) << 3);
        int nt = c_ntri[ti];
        c = (nt == 1) ? 1u : ((nt == 2) ? (1u << 16) : 0u);
    }
    __shared__ unsigned int sh[256];
    sh[threadIdx.x] = c; __syncthreads();
    #pragma unroll
    for (int o = 1; o < 256; o <<= 1) {
        unsigned int x = (threadIdx.x >= o) ? sh[threadIdx.x - o] : 0u;
        __syncthreads();
        sh[threadIdx.x] += x;
        __syncthreads();
    }
    if (t < NT) g_tloc[t] = sh[threadIdx.x] - c;   // exclusive within block
    if (threadIdx.x == 255) {
        unsigned int tot = sh[255];
        g_tblk[blockIdx.x] = (unsigned long long)(tot & 0xFFFFu)
                           | ((unsigned long long)(tot >> 16) << 32);
    }
}

// ---------------- scan of tet block sums (single block, u64 packed) ----------------
__global__ void kScanT() {
    __shared__ unsigned long long sh[1024];
    unsigned long long carry = 0;
    for (int base = 0; base < NTB; base += 1024) {
        int idx = base + threadIdx.x;
        unsigned long long val = (idx < NTB) ? g_tblk[idx] : 0ull;
        sh[threadIdx.x] = val; __syncthreads();
        for (int o = 1; o < 1024; o <<= 1) {
            unsigned long long x = (threadIdx.x >= o) ? sh[threadIdx.x - o] : 0ull;
            __syncthreads();
            sh[threadIdx.x] += x;
            __syncthreads();
        }
        if (idx < NTB) g_tblk[idx] = sh[threadIdx.x] - val + carry;
        unsigned long long tot = sh[1023];
        __syncthreads();
        carry += tot;
    }
    if (threadIdx.x == 0) g_F1 = (int)(carry & 0xFFFFFFFFull);
}

// ---------------- kernel B: emit interpolated vertices ----------------
__global__ void kB(const float* __restrict__ level, const float* __restrict__ pos,
                   const int* __restrict__ thrp, float* __restrict__ out) {
    int v = blockIdx.x * 256 + threadIdx.x;
    if (v >= NV) return;
    unsigned int mask = g_mask[v];
    if (!mask) return;
    float thr = (float)thrp[0];
    int idx = g_vloc[v] + g_vblk[blockIdx.x];
    float s0  = level[v] - thr;
    float p0x = pos[3 * v + 0], p0y = pos[3 * v + 1], p0z = pos[3 * v + 2];
    #pragma unroll
    for (int d = 1; d < 8; ++d) {
        if (mask & (1u << (d - 1))) {
            int w = v + (d >> 2) * ND2 + ((d >> 1) & 1) * NDIM + (d & 1);
            float s1 = level[w] - thr;
            float denom = s0 - s1;          // s0 + (-s1)
            float w0 = (-s1) / denom;
            float w1 = s0 / denom;
            out[3 * idx + 0] = p0x * w0 + pos[3 * w + 0] * w1;
            out[3 * idx + 1] = p0y * w0 + pos[3 * w + 1] * w1;
            out[3 * idx + 2] = p0z * w0 + pos[3 * w + 2] * w1;
            idx++;
        }
    }
}

// ---------------- kernel tB: emit faces ----------------
__global__ void ktB(const float* __restrict__ level, const int* __restrict__ tet,
                    const int* __restrict__ thrp, float* __restrict__ out) {
    int t = blockIdx.x * 256 + threadIdx.x;
    if (t >= NT) return;
    float thr = (float)thrp[0];
    int4 q = ((const int4*)tet)[t];
    int vv[4] = {q.x, q.y, q.z, q.w};
    int ti = (int)((level[q.x] - thr) > 0.0f)
           | ((int)((level[q.y] - thr) > 0.0f) << 1)
           | ((int)((level[q.z] - thr) > 0.0f) << 2)
           | ((int)((level[q.w] - thr) > 0.0f) << 3);
    int nt = c_ntri[ti];
    if (nt == 0) return;

    unsigned int       loc = g_tloc[t];
    unsigned long long blk = g_tblk[blockIdx.x];
    int fbase;
    if (nt == 1)
        fbase = (int)(loc & 0xFFFFu) + (int)(blk & 0xFFFFFFFFull);
    else
        fbase = g_F1 + 2 * ((int)(loc >> 16) + (int)(blk >> 32));

    float* fout = out + 3 * (long long)g_M;
    for (int e = 0; e < 3 * nt; ++e) {
        int le = c_tri[ti][e];
        int va = vv[(int)c_ea[le]], vb = vv[(int)c_eb[le]];
        int vmin = min(va, vb);
        int diff = max(va, vb) - vmin;
        int di = diff / ND2;
        int rem = diff - di * ND2;
        int dj = rem / NDIM;
        int dk = rem - dj * NDIM;
        int bit = di * 4 + dj * 2 + dk - 1;   // dcode-1
        int vidx = g_vloc[vmin] + g_vblk[vmin >> 8]
                 + __popc((unsigned int)g_mask[vmin] & ((1u << bit) - 1u));
        fout[3 * fbase + e] = (float)vidx;
    }
}

// ---------------- launch ----------------
extern "C" void kernel_launch(void* const* d_in, const int* in_sizes, int n_in,
                              void* d_out, int out_size) {
    const float* level = (const float*)d_in[0];
    const float* pos   = (const float*)d_in[1];
    const int*   tet   = (const int*)d_in[2];
    const int*   thrp  = (const int*)d_in[3];
    float*       out   = (float*)d_out;
    (void)in_sizes; (void)n_in; (void)out_size;

    kA   <<<NVB, 256>>>(level, thrp);
    kScanV<<<1, 1024>>>();
    ktA  <<<NTB, 256>>>(level, tet, thrp);
    kScanT<<<1, 1024>>>();
    kB   <<<NVB, 256>>>(level, pos, thrp, out);
    ktB  <<<NTB, 256>>>(level, tet, thrp, out);
}